// round 17
// baseline (speedup 1.0000x reference)
#include <cuda_runtime.h>

// Problem constants
#define BB     1024
#define TT     2048
#define DD     5
#define HH     64
#define GG     256     // 4*H gates
#define OUTN   128
#define BTILE  7
#define NGEMV  512
#define THREADS 576    // 512 GEMV + 64 updater (2 warps)
#define NCTA   147     // 147*7 = 1029 >= 1024 (last CTA: 2 valid, 5 dummy)

// Shared memory layout (bytes)
#define OFF_W1    0                 // float2[32 kp][256 g]  Whh0            65536
#define OFF_W2    65536             // float2[32 kp][256 g]  Whh1            65536
#define OFF_WX    131072            // float [5][256]  Wih0 transposed        5120
#define OFF_HC    136192            // float2[64][8]   kp0-31: h1, 32-63: h2  4096
#define OFF_PA    140288            // float[2 kh][2 chunks][1040] L1 partials 16640
#define OFF_PB    156928            // same for layer-2                      16640
#define OFF_XB    173568            // float [2][5][8] x double buffer         320
#define SMEM_BYTES 173888

// partial-sum strides (floats); R13-proven layout: P_CHUNK % 32 == 16 keeps
// the two batch-chunks on disjoint bank halves for the updater's gathers.
#define P_CHUNK  1040
#define P_KH     2080

__device__ __forceinline__ unsigned long long ffma2(unsigned long long a,
                                                    unsigned long long b,
                                                    unsigned long long c) {
    unsigned long long d;
    asm("fma.rn.f32x2 %0, %1, %2, %3;" : "=l"(d) : "l"(a), "l"(b), "l"(c));
    return d;
}

__device__ __forceinline__ float sigf(float x) {
    return __fdividef(1.0f, 1.0f + __expf(-x));
}
__device__ __forceinline__ float tanh_fast(float x) {
    return __fdividef(2.0f, 1.0f + __expf(-2.0f * x)) - 1.0f;
}

__global__ void __launch_bounds__(THREADS)
lstm_fused_kernel(const float* __restrict__ x,
                  const float* __restrict__ Wih0, const float* __restrict__ Whh0,
                  const float* __restrict__ bih0, const float* __restrict__ bhh0,
                  const float* __restrict__ Wih1, const float* __restrict__ Whh1,
                  const float* __restrict__ bih1, const float* __restrict__ bhh1,
                  const float* __restrict__ Wfc,  const float* __restrict__ bfc,
                  float* __restrict__ out)
{
    extern __shared__ char smem[];
    float2* W1f = (float2*)(smem + OFF_W1);
    float2* W2f = (float2*)(smem + OFF_W2);
    float*  WX  = (float*) (smem + OFF_WX);
    float*  HCf = (float*) (smem + OFF_HC);
    float*  PAf = (float*) (smem + OFF_PA);
    float*  PBf = (float*) (smem + OFF_PB);
    float*  XB  = (float*) (smem + OFF_XB);
    const unsigned long long* W1u = (const unsigned long long*)(smem + OFF_W1);
    const unsigned long long* W2u = (const unsigned long long*)(smem + OFF_W2);
    const ulonglong2*         HCu = (const ulonglong2*)        (smem + OFF_HC);
    const unsigned long long* HCl = (const unsigned long long*)(smem + OFF_HC);

    const int tid = threadIdx.x;
    const int g   = tid & 255;          // gate index (GEMV threads)
    const int kh  = (tid >> 8) & 1;     // k-half (GEMV threads)
    const int b0  = blockIdx.x * BTILE;
    const int kpbase = kh * 16;

    // ---- GEMV threads: Wih1 slice -> 32 REGISTERS ----
    unsigned long long w2r[16];
    {
        const unsigned long long* wi =
            (const unsigned long long*)(Wih1 + (size_t)g * HH);
        #pragma unroll
        for (int k = 0; k < 16; k++) w2r[k] = wi[kpbase + k];
    }

    // ---- Stage weights into SMEM ----
    for (int i = tid; i < GG * (HH / 2); i += THREADS) {
        int gg = i >> 5, kp = i & 31;
        W1f[kp * GG + gg] = ((const float2*)Whh0)[i];
        W2f[kp * GG + gg] = ((const float2*)Whh1)[i];
    }
    for (int i = tid; i < GG * DD; i += THREADS) {
        int gg = i / DD, d = i - gg * DD;
        WX[d * GG + gg] = Wih0[i];
    }
    for (int i = tid; i < 64 * 8 * 2; i += THREADS) HCf[i] = 0.0f;   // h1,h2

    const float breg1 = bih0[g] + bhh0[g];
    const float breg2 = bih1[g] + bhh1[g];

    // initial x staging for iteration 0
    if (tid < DD * BTILE) {
        int bbs = tid / DD, dds = tid - bbs * DD;
        int bidx = b0 + bbs; if (bidx >= BB) bidx = BB - 1;
        XB[dds * 8 + bbs] = x[((size_t)bidx * TT + 0) * DD + dds];
    }
    __syncthreads();

    // ---- updater-warp mapping (tid >= 512): 64 lanes, 8 uu-slices each ----
    const int ut    = tid - NGEMV;            // 0..63 (valid only for updaters)
    const int uwb   = (ut >> 5) * 32;         // warp base: 0 or 32
    const int uug   = (ut >> 3) & 3;          // uu sub-index 0..3
    const int ub    = ut & 7;                 // batch 0..7 (7 = idle)
    const bool uval = (tid >= NGEMV) && (ub < 7);
    const int ucb   = (ub >> 2) * P_CHUNK + (ub & 3);
    // x-prefetch lanes (on updater warps)
    const int bbx = ut / DD, ddx = ut - (ut / DD) * DD;  // valid for ut<35
    float c1s[8], c2s[8];
    #pragma unroll
    for (int i = 0; i < 8; i++) { c1s[i] = 0.0f; c2s[i] = 0.0f; }

    // ===================== Warp-specialized pipelined recurrence =====================
    // phase1(j): GEMV warps: fused gates1(j)->PA + gates2(j-1) h1-part->accB
    //            UPD warps:  x(j+1) prefetch->XB ; apply PB -> h2(j-2) [j>=2]
    //            bar A
    // phase2(j): GEMV warps: gates2(j-1) h2-part complete ->PB
    //            UPD warps:  apply PA(j)->h1(j)
    //            bar B
    unsigned long long accB[BTILE];
    for (int j = 0; j <= TT + 1; ++j) {
        const int cur = j & 1, nxt = cur ^ 1;

        if (tid < NGEMV) {
            if (j <= TT) {
                // ---------- accA init: bias + Wx.x(j) on kh0 ----------
                unsigned long long accA[BTILE];
                if (kh == 0) {
                    float sx[BTILE];
                    #pragma unroll
                    for (int b = 0; b < BTILE; b++) sx[b] = breg1;
                    const float* xrow = XB + cur * 40;
                    #pragma unroll
                    for (int d = 0; d < DD; d++) {
                        float  w  = WX[d * GG + g];
                        float4 xa = *(const float4*)(xrow + d * 8);
                        float4 xc = *(const float4*)(xrow + d * 8 + 4);
                        sx[0] += w * xa.x; sx[1] += w * xa.y; sx[2] += w * xa.z; sx[3] += w * xa.w;
                        sx[4] += w * xc.x; sx[5] += w * xc.y; sx[6] += w * xc.z;
                    }
                    #pragma unroll
                    for (int b = 0; b < BTILE; b++)
                        accA[b] = (unsigned long long)__float_as_uint(sx[b]);
                    #pragma unroll
                    for (int b = 0; b < BTILE; b++)
                        accB[b] = (unsigned long long)__float_as_uint(breg2);
                } else {
                    #pragma unroll
                    for (int b = 0; b < BTILE; b++) accA[b] = 0ull;
                    #pragma unroll
                    for (int b = 0; b < BTILE; b++) accB[b] = 0ull;
                }

                // ---- FUSED loop over h1 slice: one h load, two FFMA streams ----
                #pragma unroll
                for (int kk = 0; kk < 16; kk++) {
                    const int kp = kpbase + kk;
                    unsigned long long wA = W1u[kp * GG + g];
                    unsigned long long wB = w2r[kk];
                    ulonglong2 h01 = HCu[kp * 4 + 0];
                    ulonglong2 h23 = HCu[kp * 4 + 1];
                    ulonglong2 h45 = HCu[kp * 4 + 2];
                    unsigned long long h6 = HCl[kp * 8 + 6];
                    accA[0] = ffma2(wA, h01.x, accA[0]); accB[0] = ffma2(wB, h01.x, accB[0]);
                    accA[1] = ffma2(wA, h01.y, accA[1]); accB[1] = ffma2(wB, h01.y, accB[1]);
                    accA[2] = ffma2(wA, h23.x, accA[2]); accB[2] = ffma2(wB, h23.x, accB[2]);
                    accA[3] = ffma2(wA, h23.y, accA[3]); accB[3] = ffma2(wB, h23.y, accB[3]);
                    accA[4] = ffma2(wA, h45.x, accA[4]); accB[4] = ffma2(wB, h45.x, accB[4]);
                    accA[5] = ffma2(wA, h45.y, accA[5]); accB[5] = ffma2(wB, h45.y, accB[5]);
                    accA[6] = ffma2(wA, h6,    accA[6]); accB[6] = ffma2(wB, h6,    accB[6]);
                }
                // publish layer-1 partials
                {
                    float av[BTILE + 1];
                    #pragma unroll
                    for (int b = 0; b < BTILE; b++)
                        av[b] = __uint_as_float((unsigned)accA[b]) +
                                __uint_as_float((unsigned)(accA[b] >> 32));
                    av[7] = 0.0f;
                    float* pbase = PAf + kh * P_KH + g * 4;
                    *(float4*)(pbase)           = make_float4(av[0], av[1], av[2], av[3]);
                    *(float4*)(pbase + P_CHUNK) = make_float4(av[4], av[5], av[6], av[7]);
                }
            }
        } else {
            // ================= UPDATER warps, phase 1 =================
            // x(j+1) prefetch (issue early; store after compute)
            float xpre = 0.0f;
            if (ut < DD * BTILE) {
                int tn = (j + 1 < TT) ? (j + 1) : (TT - 1);
                int bidx = b0 + bbx; if (bidx >= BB) bidx = BB - 1;
                xpre = x[((size_t)bidx * TT + tn) * DD + ddx];
            }
            // apply PB -> h2(j-2)
            if (j >= 2 && uval) {
                const float* p0 = PBf + ucb;
                #pragma unroll
                for (int i = 0; i < 8; i++) {
                    const int uu = uwb + i * 4 + uug;
                    const int uo = uu * 4;
                    float vi = p0[uo]        + p0[P_KH + uo];
                    float vf = p0[256 + uo]  + p0[P_KH + 256 + uo];
                    float vg = p0[512 + uo]  + p0[P_KH + 512 + uo];
                    float vo = p0[768 + uo]  + p0[P_KH + 768 + uo];
                    float ai = sigf(vi), af = sigf(vf);
                    float ag = tanh_fast(vg), ao = sigf(vo);
                    c2s[i] = af * c2s[i] + ai * ag;
                    HCf[512 + (uu >> 1) * 16 + ub * 2 + (uu & 1)] = ao * tanh_fast(c2s[i]);
                }
            }
            if (ut < DD * BTILE) XB[nxt * 40 + ddx * 8 + bbx] = xpre;
        }
        __syncthreads();   // bar A

        if (j == TT + 1) break;   // final h2(TT-1) published

        if (tid < NGEMV) {
            // ================= GEMV phase 2: h2-part of gates2(j-1) =================
            #pragma unroll
            for (int kk = 0; kk < 16; kk++) {
                const int kp  = kpbase + kk;        // W2 table index 0..31
                const int kph = 32 + kp;            // h2 region in HC
                unsigned long long wB = W2u[kp * GG + g];
                ulonglong2 h01 = HCu[kph * 4 + 0];
                ulonglong2 h23 = HCu[kph * 4 + 1];
                ulonglong2 h45 = HCu[kph * 4 + 2];
                unsigned long long h6 = HCl[kph * 8 + 6];
                accB[0] = ffma2(wB, h01.x, accB[0]); accB[1] = ffma2(wB, h01.y, accB[1]);
                accB[2] = ffma2(wB, h23.x, accB[2]); accB[3] = ffma2(wB, h23.y, accB[3]);
                accB[4] = ffma2(wB, h45.x, accB[4]); accB[5] = ffma2(wB, h45.y, accB[5]);
                accB[6] = ffma2(wB, h6,    accB[6]);
            }
            {
                float av[BTILE + 1];
                #pragma unroll
                for (int b = 0; b < BTILE; b++)
                    av[b] = __uint_as_float((unsigned)accB[b]) +
                            __uint_as_float((unsigned)(accB[b] >> 32));
                av[7] = 0.0f;
                float* pbase = PBf + kh * P_KH + g * 4;
                *(float4*)(pbase)           = make_float4(av[0], av[1], av[2], av[3]);
                *(float4*)(pbase + P_CHUNK) = make_float4(av[4], av[5], av[6], av[7]);
            }
        } else {
            // ================= UPDATER warps, phase 2: apply PA(j) -> h1(j) =================
            if (uval) {
                const float* p0 = PAf + ucb;
                #pragma unroll
                for (int i = 0; i < 8; i++) {
                    const int uu = uwb + i * 4 + uug;
                    const int uo = uu * 4;
                    float vi = p0[uo]        + p0[P_KH + uo];
                    float vf = p0[256 + uo]  + p0[P_KH + 256 + uo];
                    float vg = p0[512 + uo]  + p0[P_KH + 512 + uo];
                    float vo = p0[768 + uo]  + p0[P_KH + 768 + uo];
                    float ai = sigf(vi), af = sigf(vf);
                    float ag = tanh_fast(vg), ao = sigf(vo);
                    c1s[i] = af * c1s[i] + ai * ag;
                    HCf[(uu >> 1) * 16 + ub * 2 + (uu & 1)] = ao * tanh_fast(c1s[i]);
                }
            }
        }
        __syncthreads();   // bar B
    }

    // ========= Fused FC + ReLU: out[b][o] = relu(h2[b] . Wfc[o] + bfc[o]) =========
    // (bar A of the final iteration ordered the last h2 writes.)
    if (tid < 32 * BTILE) {
        const int b  = tid >> 5;
        const int o  = (tid & 31) * 4;
        const int bidx = b0 + b;
        if (bidx < BB) {
            const float* w0 = Wfc + (size_t)(o + 0) * HH;
            const float* w1 = Wfc + (size_t)(o + 1) * HH;
            const float* w2 = Wfc + (size_t)(o + 2) * HH;
            const float* w3 = Wfc + (size_t)(o + 3) * HH;
            float s0 = bfc[o], s1 = bfc[o + 1], s2 = bfc[o + 2], s3 = bfc[o + 3];
            #pragma unroll
            for (int u = 0; u < HH; u++) {
                float h = HCf[512 + (u >> 1) * 16 + b * 2 + (u & 1)];
                s0 += h * w0[u]; s1 += h * w1[u]; s2 += h * w2[u]; s3 += h * w3[u];
            }
            float4 r = make_float4(fmaxf(s0, 0.f), fmaxf(s1, 0.f),
                                   fmaxf(s2, 0.f), fmaxf(s3, 0.f));
            *(float4*)(out + (size_t)bidx * OUTN + o) = r;
        }
    }
}

extern "C" void kernel_launch(void* const* d_in, const int* in_sizes, int n_in,
                              void* d_out, int out_size)
{
    const float* x    = (const float*)d_in[0];
    const float* Wih0 = (const float*)d_in[1];
    const float* Whh0 = (const float*)d_in[2];
    const float* bih0 = (const float*)d_in[3];
    const float* bhh0 = (const float*)d_in[4];
    const float* Wih1 = (const float*)d_in[5];
    const float* Whh1 = (const float*)d_in[6];
    const float* bih1 = (const float*)d_in[7];
    const float* bhh1 = (const float*)d_in[8];
    const float* Wfc  = (const float*)d_in[9];
    const float* bfc  = (const float*)d_in[10];
    float* out = (float*)d_out;

    cudaFuncSetAttribute(lstm_fused_kernel,
                         cudaFuncAttributeMaxDynamicSharedMemorySize, SMEM_BYTES);

    lstm_fused_kernel<<<NCTA, THREADS, SMEM_BYTES>>>(
        x, Wih0, Whh0, bih0, bhh0, Wih1, Whh1, bih1, bhh1, Wfc, bfc, out);
}